// round 4
// baseline (speedup 1.0000x reference)
#include <cuda_runtime.h>

#define C 64
#define MAXN 50000
#define MAXE 800000
#define LN_EPS 1e-5f
#define GN_EPS 1e-5f

// Scratch (no allocs allowed in kernel_launch)
__device__ float g_agg[(size_t)MAXN * C];
__device__ float g_h2[(size_t)MAXN * C];
__device__ float g_S1[C];
__device__ float g_S2[C];
__device__ float g_A[C];
__device__ float g_B[C];

// ---------------------------------------------------------------------------
// K0: zero agg + stats
// ---------------------------------------------------------------------------
__global__ void k_zero(float4* agg4, long long n4, float* s1, float* s2) {
    long long i = (long long)blockIdx.x * blockDim.x + threadIdx.x;
    long long stride = (long long)gridDim.x * blockDim.x;
    float4 z = make_float4(0.f, 0.f, 0.f, 0.f);
    for (long long j = i; j < n4; j += stride) agg4[j] = z;
    if (i < C) { s1[i] = 0.f; s2[i] = 0.f; }
}

// ---------------------------------------------------------------------------
// Detect whether the edge_index buffer is int64 or int32.
// If int32 data is misread as int64, each value packs two random indices
// (lo + hi*2^32) and is astronomically out of [0, N) range.
// ---------------------------------------------------------------------------
__device__ __forceinline__ bool ei_is_int64(const long long* ei, int N) {
    bool ok = true;
    #pragma unroll
    for (int i = 0; i < 4; i++) {
        long long v = __ldg(ei + i);
        ok = ok && (v >= 0) && (v < (long long)N);
    }
    return ok;
}

// ---------------------------------------------------------------------------
// K1: scatter-add   agg[dst] += x[src]   (16 threads per edge, float4 gather)
// ---------------------------------------------------------------------------
__global__ void k_scatter(const float* __restrict__ x,
                          const long long* __restrict__ ei,
                          float* __restrict__ agg, int E, int N) {
    long long tid = (long long)blockIdx.x * blockDim.x + threadIdx.x;
    int e = (int)(tid >> 4);
    if (e >= E) return;
    int g = (int)(tid & 15);

    int s, d;
    if (ei_is_int64(ei, N)) {
        s = (int)__ldg(ei + e);
        d = (int)__ldg(ei + (long long)E + e);
    } else {
        const int* ei32 = (const int*)ei;
        s = __ldg(ei32 + e);
        d = __ldg(ei32 + (long long)E + e);
    }
    if ((unsigned)s >= (unsigned)N || (unsigned)d >= (unsigned)N) return;

    float4 v = __ldg((const float4*)(x + (long long)s * C) + g);
    float* a = agg + (long long)d * C + g * 4;
    atomicAdd(a + 0, v.x);
    atomicAdd(a + 1, v.y);
    atomicAdd(a + 2, v.z);
    atomicAdd(a + 3, v.w);
}

// ---------------------------------------------------------------------------
// K2: per-node MLP (warp per node) + fused GraphNorm partial sums
//   h = x + agg
//   h = relu(LN(h @ W0^T)); h = relu(LN(h @ W1^T))
//   S1[c] += sum_n h[n,c];  S2[c] += sum_n h[n,c]^2
// ---------------------------------------------------------------------------
__global__ __launch_bounds__(256) void k_mlp(
    const float* __restrict__ x, const float* __restrict__ agg,
    const float* __restrict__ W0, const float* __restrict__ ln0w, const float* __restrict__ ln0b,
    const float* __restrict__ W1, const float* __restrict__ ln1w, const float* __restrict__ ln1b,
    float* __restrict__ h2, float* __restrict__ S1, float* __restrict__ S2, int N) {

    __shared__ float sW0[64 * 65];   // transposed, padded: sW0[k*65+c] = W0[c,k]
    __shared__ float sW1[64 * 65];
    __shared__ float sh[8][64];
    __shared__ float sS1[64], sS2[64];

    int tid = threadIdx.x;
    for (int i = tid; i < 4096; i += 256) {
        int c = i >> 6, k = i & 63;
        sW0[k * 65 + c] = W0[i];
        sW1[k * 65 + c] = W1[i];
    }
    if (tid < 64) { sS1[tid] = 0.f; sS2[tid] = 0.f; }
    __syncthreads();

    int w = tid >> 5, l = tid & 31;
    int n = blockIdx.x * 8 + w;

    if (n < N) {
        long long base = (long long)n * C;
        float h0 = x[base + l]      + agg[base + l];
        float h1 = x[base + 32 + l] + agg[base + 32 + l];

        // ---- GEMM1: o[c] = sum_k h[k] * W0[c,k] ----
        sh[w][l] = h0; sh[w][l + 32] = h1;
        __syncwarp();
        float o0 = 0.f, o1 = 0.f;
        #pragma unroll
        for (int k = 0; k < 64; k++) {
            float hv = sh[w][k];
            o0 = fmaf(hv, sW0[k * 65 + l],      o0);
            o1 = fmaf(hv, sW0[k * 65 + l + 32], o1);
        }
        // ---- LN0 + ReLU ----
        float s = o0 + o1, sq = o0 * o0 + o1 * o1;
        #pragma unroll
        for (int m = 16; m > 0; m >>= 1) {
            s  += __shfl_xor_sync(0xffffffff, s,  m);
            sq += __shfl_xor_sync(0xffffffff, sq, m);
        }
        float mu  = s * (1.f / 64.f);
        float var = sq * (1.f / 64.f) - mu * mu;
        float inv = rsqrtf(var + LN_EPS);
        o0 = fmaxf(fmaf((o0 - mu) * inv, __ldg(ln0w + l),      __ldg(ln0b + l)),      0.f);
        o1 = fmaxf(fmaf((o1 - mu) * inv, __ldg(ln0w + l + 32), __ldg(ln0b + l + 32)), 0.f);

        // ---- GEMM2 ----
        __syncwarp();
        sh[w][l] = o0; sh[w][l + 32] = o1;
        __syncwarp();
        float p0 = 0.f, p1 = 0.f;
        #pragma unroll
        for (int k = 0; k < 64; k++) {
            float hv = sh[w][k];
            p0 = fmaf(hv, sW1[k * 65 + l],      p0);
            p1 = fmaf(hv, sW1[k * 65 + l + 32], p1);
        }
        // ---- LN1 + ReLU ----
        s = p0 + p1; sq = p0 * p0 + p1 * p1;
        #pragma unroll
        for (int m = 16; m > 0; m >>= 1) {
            s  += __shfl_xor_sync(0xffffffff, s,  m);
            sq += __shfl_xor_sync(0xffffffff, sq, m);
        }
        mu  = s * (1.f / 64.f);
        var = sq * (1.f / 64.f) - mu * mu;
        inv = rsqrtf(var + LN_EPS);
        float r0 = fmaxf(fmaf((p0 - mu) * inv, __ldg(ln1w + l),      __ldg(ln1b + l)),      0.f);
        float r1 = fmaxf(fmaf((p1 - mu) * inv, __ldg(ln1w + l + 32), __ldg(ln1b + l + 32)), 0.f);

        h2[base + l]      = r0;
        h2[base + 32 + l] = r1;

        atomicAdd(&sS1[l],      r0);
        atomicAdd(&sS1[l + 32], r1);
        atomicAdd(&sS2[l],      r0 * r0);
        atomicAdd(&sS2[l + 32], r1 * r1);
    }
    __syncthreads();
    if (tid < 64) {
        atomicAdd(&S1[tid], sS1[tid]);
        atomicAdd(&S2[tid], sS2[tid]);
    }
}

// ---------------------------------------------------------------------------
// K3: finalize per-channel affine  out = A[c]*h + B[c]
// ---------------------------------------------------------------------------
__global__ void k_stats(const float* __restrict__ S1, const float* __restrict__ S2,
                        const float* __restrict__ gw, const float* __restrict__ gb,
                        const float* __restrict__ ga,
                        float* __restrict__ A, float* __restrict__ B, float invN) {
    int c = threadIdx.x;
    if (c >= C) return;
    float m  = S1[c] * invN;
    float e2 = S2[c] * invN;
    float a  = ga[c];
    float var = e2 - 2.f * a * m * m + a * a * m * m;
    float inv = rsqrtf(var + GN_EPS);
    float Ac  = gw[c] * inv;
    A[c] = Ac;
    B[c] = gb[c] - Ac * a * m;
}

// ---------------------------------------------------------------------------
// K4: apply GraphNorm elementwise (float4)
// ---------------------------------------------------------------------------
__global__ void k_apply(const float4* __restrict__ h4,
                        const float* __restrict__ A, const float* __restrict__ B,
                        float4* __restrict__ out4, long long n4) {
    __shared__ float sA[64], sB[64];
    if (threadIdx.x < 64) { sA[threadIdx.x] = A[threadIdx.x]; sB[threadIdx.x] = B[threadIdx.x]; }
    __syncthreads();
    long long i = (long long)blockIdx.x * blockDim.x + threadIdx.x;
    long long stride = (long long)gridDim.x * blockDim.x;
    for (long long j = i; j < n4; j += stride) {
        float4 v = h4[j];
        int c = (int)((j * 4) & 63);
        v.x = fmaf(sA[c + 0], v.x, sB[c + 0]);
        v.y = fmaf(sA[c + 1], v.y, sB[c + 1]);
        v.z = fmaf(sA[c + 2], v.z, sB[c + 2]);
        v.w = fmaf(sA[c + 3], v.w, sB[c + 3]);
        out4[j] = v;
    }
}

// ---------------------------------------------------------------------------
extern "C" void kernel_launch(void* const* d_in, const int* in_sizes, int n_in,
                              void* d_out, int out_size) {
    const float*     x    = (const float*)d_in[0];
    const long long* ei   = (const long long*)d_in[1];
    const float*     W0   = (const float*)d_in[2];
    const float*     ln0w = (const float*)d_in[3];
    const float*     ln0b = (const float*)d_in[4];
    const float*     W1   = (const float*)d_in[5];
    const float*     ln1w = (const float*)d_in[6];
    const float*     ln1b = (const float*)d_in[7];
    const float*     gnw  = (const float*)d_in[8];
    const float*     gnb  = (const float*)d_in[9];
    const float*     gna  = (const float*)d_in[10];
    float*           out  = (float*)d_out;

    int N = in_sizes[0] / C;
    int E = in_sizes[1] / 2;
    if (N > MAXN) N = MAXN;
    if (E > MAXE) E = MAXE;

    float *agg, *h2, *S1, *S2, *A, *B;
    cudaGetSymbolAddress((void**)&agg, g_agg);
    cudaGetSymbolAddress((void**)&h2,  g_h2);
    cudaGetSymbolAddress((void**)&S1,  g_S1);
    cudaGetSymbolAddress((void**)&S2,  g_S2);
    cudaGetSymbolAddress((void**)&A,   g_A);
    cudaGetSymbolAddress((void**)&B,   g_B);

    long long nelem = (long long)N * C;
    long long n4 = nelem / 4;

    // K0: zero agg + stats
    {
        int blocks = (int)((n4 + 255) / 256);
        if (blocks > 1184) blocks = 1184;
        k_zero<<<blocks, 256>>>((float4*)agg, n4, S1, S2);
    }
    // K1: scatter-add
    {
        long long threads = (long long)E * 16;
        int blocks = (int)((threads + 255) / 256);
        k_scatter<<<blocks, 256>>>(x, ei, agg, E, N);
    }
    // K2: MLP + partial GraphNorm stats
    {
        int blocks = (N + 7) / 8;
        k_mlp<<<blocks, 256>>>(x, agg, W0, ln0w, ln0b, W1, ln1w, ln1b,
                               h2, S1, S2, N);
    }
    // K3: finalize affine params
    k_stats<<<1, 64>>>(S1, S2, gnw, gnb, gna, A, B, 1.0f / (float)N);
    // K4: apply
    {
        int blocks = (int)((n4 + 255) / 256);
        if (blocks > 1184) blocks = 1184;
        k_apply<<<blocks, 256>>>((const float4*)h2, A, B, (float4*)out, n4);
    }
}

// round 5
// speedup vs baseline: 1.6392x; 1.6392x over previous
#include <cuda_runtime.h>

#define C 64
#define MAXN 50000
#define MAXE 800000
#define LN_EPS 1e-5f
#define GN_EPS 1e-5f

// Scratch (no allocs allowed in kernel_launch)
__device__ float g_agg[(size_t)MAXN * C];
__device__ float g_h2[(size_t)MAXN * C];
__device__ float g_S1[C];
__device__ float g_S2[C];
__device__ float g_A[C];
__device__ float g_B[C];

// ---------------------------------------------------------------------------
// K0: zero agg + stats
// ---------------------------------------------------------------------------
__global__ void k_zero(float4* agg4, long long n4, float* s1, float* s2) {
    long long i = (long long)blockIdx.x * blockDim.x + threadIdx.x;
    long long stride = (long long)gridDim.x * blockDim.x;
    float4 z = make_float4(0.f, 0.f, 0.f, 0.f);
    for (long long j = i; j < n4; j += stride) agg4[j] = z;
    if (i < C) { s1[i] = 0.f; s2[i] = 0.f; }
}

// ---------------------------------------------------------------------------
// Detect whether the edge_index buffer is int64 or int32 (JAX x64-disable
// silently narrows). int32 misread as int64 is astronomically out of range.
// ---------------------------------------------------------------------------
__device__ __forceinline__ bool ei_is_int64(const long long* ei, int N) {
    bool ok = true;
    #pragma unroll
    for (int i = 0; i < 4; i++) {
        long long v = __ldg(ei + i);
        ok = ok && (v >= 0) && (v < (long long)N);
    }
    return ok;
}

// ---------------------------------------------------------------------------
// K1: scatter-add   agg[dst] += x[src]
//   16 threads per edge, each does ONE vector atomic (float4) -> 12.8M reds
//   instead of 51.2M scalar reds.
// ---------------------------------------------------------------------------
__global__ void k_scatter(const float* __restrict__ x,
                          const long long* __restrict__ ei,
                          float* __restrict__ agg, int E, int N) {
    long long tid = (long long)blockIdx.x * blockDim.x + threadIdx.x;
    int e = (int)(tid >> 4);
    if (e >= E) return;
    int g = (int)(tid & 15);

    int s, d;
    if (ei_is_int64(ei, N)) {
        s = (int)__ldg(ei + e);
        d = (int)__ldg(ei + (long long)E + e);
    } else {
        const int* ei32 = (const int*)ei;
        s = __ldg(ei32 + e);
        d = __ldg(ei32 + (long long)E + e);
    }
    if ((unsigned)s >= (unsigned)N || (unsigned)d >= (unsigned)N) return;

    float4 v = __ldg((const float4*)(x + (long long)s * C) + g);
    float4* a4 = (float4*)(agg + (long long)d * C) + g;
    atomicAdd(a4, v);   // RED.E.ADD.V4.F32 (sm_90+)
}

// ---------------------------------------------------------------------------
// K2: per-node MLP (warp per node, persistent blocks) + GraphNorm partials
// ---------------------------------------------------------------------------
__global__ __launch_bounds__(256) void k_mlp(
    const float* __restrict__ x, const float* __restrict__ agg,
    const float* __restrict__ W0, const float* __restrict__ ln0w, const float* __restrict__ ln0b,
    const float* __restrict__ W1, const float* __restrict__ ln1w, const float* __restrict__ ln1b,
    float* __restrict__ h2, float* __restrict__ S1, float* __restrict__ S2, int N) {

    __shared__ float sW0[64 * 65];   // transposed, padded: sW0[k*65+c] = W0[c,k]
    __shared__ float sW1[64 * 65];
    __shared__ float sh[8][64];
    __shared__ float sS1[64], sS2[64];

    int tid = threadIdx.x;
    for (int i = tid; i < 4096; i += 256) {
        int c = i >> 6, k = i & 63;
        sW0[k * 65 + c] = W0[i];
        sW1[k * 65 + c] = W1[i];
    }
    if (tid < 64) { sS1[tid] = 0.f; sS2[tid] = 0.f; }
    __syncthreads();

    int w = tid >> 5, l = tid & 31;
    float ln0w0 = __ldg(ln0w + l),      ln0b0 = __ldg(ln0b + l);
    float ln0w1 = __ldg(ln0w + l + 32), ln0b1 = __ldg(ln0b + l + 32);
    float ln1w0 = __ldg(ln1w + l),      ln1b0 = __ldg(ln1b + l);
    float ln1w1 = __ldg(ln1w + l + 32), ln1b1 = __ldg(ln1b + l + 32);

    float accS1_0 = 0.f, accS1_1 = 0.f, accS2_0 = 0.f, accS2_1 = 0.f;

    int groups = (N + 7) >> 3;
    for (int gi = blockIdx.x; gi < groups; gi += gridDim.x) {
        int n = gi * 8 + w;
        if (n < N) {
            long long base = (long long)n * C;
            float h0 = x[base + l]      + agg[base + l];
            float h1 = x[base + 32 + l] + agg[base + 32 + l];

            // ---- GEMM1 ----
            sh[w][l] = h0; sh[w][l + 32] = h1;
            __syncwarp();
            float o0 = 0.f, o1 = 0.f;
            #pragma unroll
            for (int k = 0; k < 64; k++) {
                float hv = sh[w][k];
                o0 = fmaf(hv, sW0[k * 65 + l],      o0);
                o1 = fmaf(hv, sW0[k * 65 + l + 32], o1);
            }
            // ---- LN0 + ReLU ----
            float s = o0 + o1, sq = o0 * o0 + o1 * o1;
            #pragma unroll
            for (int m = 16; m > 0; m >>= 1) {
                s  += __shfl_xor_sync(0xffffffff, s,  m);
                sq += __shfl_xor_sync(0xffffffff, sq, m);
            }
            float mu  = s * (1.f / 64.f);
            float var = sq * (1.f / 64.f) - mu * mu;
            float inv = rsqrtf(var + LN_EPS);
            o0 = fmaxf(fmaf((o0 - mu) * inv, ln0w0, ln0b0), 0.f);
            o1 = fmaxf(fmaf((o1 - mu) * inv, ln0w1, ln0b1), 0.f);

            // ---- GEMM2 ----
            __syncwarp();
            sh[w][l] = o0; sh[w][l + 32] = o1;
            __syncwarp();
            float p0 = 0.f, p1 = 0.f;
            #pragma unroll
            for (int k = 0; k < 64; k++) {
                float hv = sh[w][k];
                p0 = fmaf(hv, sW1[k * 65 + l],      p0);
                p1 = fmaf(hv, sW1[k * 65 + l + 32], p1);
            }
            // ---- LN1 + ReLU ----
            s = p0 + p1; sq = p0 * p0 + p1 * p1;
            #pragma unroll
            for (int m = 16; m > 0; m >>= 1) {
                s  += __shfl_xor_sync(0xffffffff, s,  m);
                sq += __shfl_xor_sync(0xffffffff, sq, m);
            }
            mu  = s * (1.f / 64.f);
            var = sq * (1.f / 64.f) - mu * mu;
            inv = rsqrtf(var + LN_EPS);
            float r0 = fmaxf(fmaf((p0 - mu) * inv, ln1w0, ln1b0), 0.f);
            float r1 = fmaxf(fmaf((p1 - mu) * inv, ln1w1, ln1b1), 0.f);

            h2[base + l]      = r0;
            h2[base + 32 + l] = r1;

            accS1_0 += r0; accS1_1 += r1;
            accS2_0 += r0 * r0; accS2_1 += r1 * r1;
            __syncwarp();
        }
    }

    // per-block reduce into shared, then 64 global atomics per block
    atomicAdd(&sS1[l],      accS1_0);
    atomicAdd(&sS1[l + 32], accS1_1);
    atomicAdd(&sS2[l],      accS2_0);
    atomicAdd(&sS2[l + 32], accS2_1);
    __syncthreads();
    if (tid < 64) {
        atomicAdd(&S1[tid], sS1[tid]);
        atomicAdd(&S2[tid], sS2[tid]);
    }
}

// ---------------------------------------------------------------------------
// K3: finalize per-channel affine  out = A[c]*h + B[c]
// ---------------------------------------------------------------------------
__global__ void k_stats(const float* __restrict__ S1, const float* __restrict__ S2,
                        const float* __restrict__ gw, const float* __restrict__ gb,
                        const float* __restrict__ ga,
                        float* __restrict__ A, float* __restrict__ B, float invN) {
    int c = threadIdx.x;
    if (c >= C) return;
    float m  = S1[c] * invN;
    float e2 = S2[c] * invN;
    float a  = ga[c];
    float var = e2 - 2.f * a * m * m + a * a * m * m;
    float inv = rsqrtf(var + GN_EPS);
    float Ac  = gw[c] * inv;
    A[c] = Ac;
    B[c] = gb[c] - Ac * a * m;
}

// ---------------------------------------------------------------------------
// K4: apply GraphNorm elementwise (float4)
// ---------------------------------------------------------------------------
__global__ void k_apply(const float4* __restrict__ h4,
                        const float* __restrict__ A, const float* __restrict__ B,
                        float4* __restrict__ out4, long long n4) {
    __shared__ float sA[64], sB[64];
    if (threadIdx.x < 64) { sA[threadIdx.x] = A[threadIdx.x]; sB[threadIdx.x] = B[threadIdx.x]; }
    __syncthreads();
    long long i = (long long)blockIdx.x * blockDim.x + threadIdx.x;
    long long stride = (long long)gridDim.x * blockDim.x;
    for (long long j = i; j < n4; j += stride) {
        float4 v = h4[j];
        int c = (int)((j * 4) & 63);
        v.x = fmaf(sA[c + 0], v.x, sB[c + 0]);
        v.y = fmaf(sA[c + 1], v.y, sB[c + 1]);
        v.z = fmaf(sA[c + 2], v.z, sB[c + 2]);
        v.w = fmaf(sA[c + 3], v.w, sB[c + 3]);
        out4[j] = v;
    }
}

// ---------------------------------------------------------------------------
extern "C" void kernel_launch(void* const* d_in, const int* in_sizes, int n_in,
                              void* d_out, int out_size) {
    const float*     x    = (const float*)d_in[0];
    const long long* ei   = (const long long*)d_in[1];
    const float*     W0   = (const float*)d_in[2];
    const float*     ln0w = (const float*)d_in[3];
    const float*     ln0b = (const float*)d_in[4];
    const float*     W1   = (const float*)d_in[5];
    const float*     ln1w = (const float*)d_in[6];
    const float*     ln1b = (const float*)d_in[7];
    const float*     gnw  = (const float*)d_in[8];
    const float*     gnb  = (const float*)d_in[9];
    const float*     gna  = (const float*)d_in[10];
    float*           out  = (float*)d_out;

    int N = in_sizes[0] / C;
    int E = in_sizes[1] / 2;
    if (N > MAXN) N = MAXN;
    if (E > MAXE) E = MAXE;

    float *agg, *h2, *S1, *S2, *A, *B;
    cudaGetSymbolAddress((void**)&agg, g_agg);
    cudaGetSymbolAddress((void**)&h2,  g_h2);
    cudaGetSymbolAddress((void**)&S1,  g_S1);
    cudaGetSymbolAddress((void**)&S2,  g_S2);
    cudaGetSymbolAddress((void**)&A,   g_A);
    cudaGetSymbolAddress((void**)&B,   g_B);

    long long nelem = (long long)N * C;
    long long n4 = nelem / 4;

    // K0: zero agg + stats
    {
        int blocks = (int)((n4 + 255) / 256);
        if (blocks > 1184) blocks = 1184;
        k_zero<<<blocks, 256>>>((float4*)agg, n4, S1, S2);
    }
    // K1: scatter-add (vector atomics)
    {
        long long threads = (long long)E * 16;
        int blocks = (int)((threads + 255) / 256);
        k_scatter<<<blocks, 256>>>(x, ei, agg, E, N);
    }
    // K2: MLP + partial GraphNorm stats (persistent blocks)
    {
        int groups = (N + 7) / 8;
        int blocks = groups < 592 ? groups : 592;
        k_mlp<<<blocks, 256>>>(x, agg, W0, ln0w, ln0b, W1, ln1w, ln1b,
                               h2, S1, S2, N);
    }
    // K3: finalize affine params
    k_stats<<<1, 64>>>(S1, S2, gnw, gnb, gna, A, B, 1.0f / (float)N);
    // K4: apply
    {
        int blocks = (int)((n4 + 255) / 256);
        if (blocks > 1184) blocks = 1184;
        k_apply<<<blocks, 256>>>((const float4*)h2, A, B, (float4*)out, n4);
    }
}

// round 6
// speedup vs baseline: 1.9492x; 1.1892x over previous
#include <cuda_runtime.h>

#define C 64
#define MAXN 50000
#define MAXE 800000
#define LN_EPS 1e-5f
#define GN_EPS 1e-5f

// Scratch (no allocs allowed in kernel_launch)
__device__ float g_agg[(size_t)MAXN * C];
__device__ float g_h2[(size_t)MAXN * C];
__device__ float g_S1[C];
__device__ float g_S2[C];

// ---------------------------------------------------------------------------
// K0: agg = x (so GIN h = x + sum becomes just agg after scatter), zero stats
// ---------------------------------------------------------------------------
__global__ void k_init(const float4* __restrict__ x4, float4* __restrict__ agg4,
                       long long n4, float* s1, float* s2) {
    long long i = (long long)blockIdx.x * blockDim.x + threadIdx.x;
    long long stride = (long long)gridDim.x * blockDim.x;
    for (long long j = i; j < n4; j += stride) agg4[j] = x4[j];
    if (i < C) { s1[i] = 0.f; s2[i] = 0.f; }
}

// ---------------------------------------------------------------------------
// Detect whether the edge_index buffer is int64 or int32 (JAX x64-disable
// silently narrows). int32 misread as int64 is astronomically out of range.
// ---------------------------------------------------------------------------
__device__ __forceinline__ bool ei_is_int64(const long long* ei, int N) {
    bool ok = true;
    #pragma unroll
    for (int i = 0; i < 4; i++) {
        long long v = __ldg(ei + i);
        ok = ok && (v >= 0) && (v < (long long)N);
    }
    return ok;
}

// ---------------------------------------------------------------------------
// K1: scatter-add   agg[dst] += x[src]   (16 threads/edge, float4 vector red)
// ---------------------------------------------------------------------------
__global__ void k_scatter(const float* __restrict__ x,
                          const long long* __restrict__ ei,
                          float* __restrict__ agg, int E, int N) {
    long long tid = (long long)blockIdx.x * blockDim.x + threadIdx.x;
    int e = (int)(tid >> 4);
    if (e >= E) return;
    int g = (int)(tid & 15);

    int s, d;
    if (ei_is_int64(ei, N)) {
        s = (int)__ldg(ei + e);
        d = (int)__ldg(ei + (long long)E + e);
    } else {
        const int* ei32 = (const int*)ei;
        s = __ldg(ei32 + e);
        d = __ldg(ei32 + (long long)E + e);
    }
    if ((unsigned)s >= (unsigned)N || (unsigned)d >= (unsigned)N) return;

    float4 v = __ldg((const float4*)(x + (long long)s * C) + g);
    float4* a4 = (float4*)(agg + (long long)d * C) + g;
    atomicAdd(a4, v);   // RED.E.ADD.V4.F32
}

// ---------------------------------------------------------------------------
// K2: per-node MLP, 4 nodes per warp (FMA-bound), persistent blocks,
//     fused GraphNorm partial sums.
//   h (=x+agg already) -> relu(LN(h@W0^T)) -> relu(LN(.@W1^T)) -> h2, S1, S2
// ---------------------------------------------------------------------------
__global__ __launch_bounds__(256) void k_mlp(
    const float* __restrict__ agg,
    const float* __restrict__ W0, const float* __restrict__ ln0w, const float* __restrict__ ln0b,
    const float* __restrict__ W1, const float* __restrict__ ln1w, const float* __restrict__ ln1b,
    float* __restrict__ h2, float* __restrict__ S1, float* __restrict__ S2, int N) {

    // sWv[k*32 + l] = (W[l][k], W[l+32][k])  (transposed, vectorized)
    __shared__ float2 sW0v[64 * 32];
    __shared__ float2 sW1v[64 * 32];
    __shared__ float4 shb[8][64];       // shb[w][k] = h[k] for 4 nodes of warp w
    __shared__ float sS1[64], sS2[64];

    int tid = threadIdx.x;
    for (int i = tid; i < 2048; i += 256) {
        int k = i >> 5, l = i & 31;
        sW0v[i] = make_float2(W0[l * 64 + k], W0[(l + 32) * 64 + k]);
        sW1v[i] = make_float2(W1[l * 64 + k], W1[(l + 32) * 64 + k]);
    }
    if (tid < 64) { sS1[tid] = 0.f; sS2[tid] = 0.f; }
    __syncthreads();

    int w = tid >> 5, l = tid & 31;
    float p0w = __ldg(ln0w + l),      p0b = __ldg(ln0b + l);
    float p1w = __ldg(ln0w + l + 32), p1b = __ldg(ln0b + l + 32);
    float q0w = __ldg(ln1w + l),      q0b = __ldg(ln1b + l);
    float q1w = __ldg(ln1w + l + 32), q1b = __ldg(ln1b + l + 32);

    float accS1_0 = 0.f, accS1_1 = 0.f, accS2_0 = 0.f, accS2_1 = 0.f;

    int groups = (N + 31) >> 5;          // 32 nodes per block-iteration
    for (int gi = blockIdx.x; gi < groups; gi += gridDim.x) {
        int nbase = gi * 32 + w * 4;

        // ---- load h (4 nodes) ----
        float h0[4], h1[4];
        #pragma unroll
        for (int j = 0; j < 4; j++) {
            int n = nbase + j;
            if (n < N) {
                long long b = (long long)n * C;
                h0[j] = agg[b + l];
                h1[j] = agg[b + 32 + l];
            } else { h0[j] = 0.f; h1[j] = 0.f; }
        }
        shb[w][l]      = make_float4(h0[0], h0[1], h0[2], h0[3]);
        shb[w][l + 32] = make_float4(h1[0], h1[1], h1[2], h1[3]);
        __syncwarp();

        // ---- GEMM1: o[c] = sum_k h[k] * W0[c][k] ----
        float o0[4] = {0.f,0.f,0.f,0.f}, o1[4] = {0.f,0.f,0.f,0.f};
        #pragma unroll
        for (int k = 0; k < 64; k++) {
            float4 hv = shb[w][k];
            float2 wv = sW0v[k * 32 + l];
            o0[0] = fmaf(hv.x, wv.x, o0[0]); o1[0] = fmaf(hv.x, wv.y, o1[0]);
            o0[1] = fmaf(hv.y, wv.x, o0[1]); o1[1] = fmaf(hv.y, wv.y, o1[1]);
            o0[2] = fmaf(hv.z, wv.x, o0[2]); o1[2] = fmaf(hv.z, wv.y, o1[2]);
            o0[3] = fmaf(hv.w, wv.x, o0[3]); o1[3] = fmaf(hv.w, wv.y, o1[3]);
        }

        // ---- LN0 + ReLU (4 nodes) ----
        {
            float s[4], q[4];
            #pragma unroll
            for (int j = 0; j < 4; j++) {
                s[j] = o0[j] + o1[j];
                q[j] = o0[j] * o0[j] + o1[j] * o1[j];
            }
            #pragma unroll
            for (int m = 16; m > 0; m >>= 1) {
                #pragma unroll
                for (int j = 0; j < 4; j++) {
                    s[j] += __shfl_xor_sync(0xffffffff, s[j], m);
                    q[j] += __shfl_xor_sync(0xffffffff, q[j], m);
                }
            }
            #pragma unroll
            for (int j = 0; j < 4; j++) {
                float mu  = s[j] * (1.f / 64.f);
                float var = q[j] * (1.f / 64.f) - mu * mu;
                float inv = rsqrtf(var + LN_EPS);
                o0[j] = fmaxf(fmaf((o0[j] - mu) * inv, p0w, p0b), 0.f);
                o1[j] = fmaxf(fmaf((o1[j] - mu) * inv, p1w, p1b), 0.f);
            }
        }

        // ---- GEMM2 ----
        __syncwarp();
        shb[w][l]      = make_float4(o0[0], o0[1], o0[2], o0[3]);
        shb[w][l + 32] = make_float4(o1[0], o1[1], o1[2], o1[3]);
        __syncwarp();
        float r0[4] = {0.f,0.f,0.f,0.f}, r1[4] = {0.f,0.f,0.f,0.f};
        #pragma unroll
        for (int k = 0; k < 64; k++) {
            float4 hv = shb[w][k];
            float2 wv = sW1v[k * 32 + l];
            r0[0] = fmaf(hv.x, wv.x, r0[0]); r1[0] = fmaf(hv.x, wv.y, r1[0]);
            r0[1] = fmaf(hv.y, wv.x, r0[1]); r1[1] = fmaf(hv.y, wv.y, r1[1]);
            r0[2] = fmaf(hv.z, wv.x, r0[2]); r1[2] = fmaf(hv.z, wv.y, r1[2]);
            r0[3] = fmaf(hv.w, wv.x, r0[3]); r1[3] = fmaf(hv.w, wv.y, r1[3]);
        }

        // ---- LN1 + ReLU (4 nodes) ----
        {
            float s[4], q[4];
            #pragma unroll
            for (int j = 0; j < 4; j++) {
                s[j] = r0[j] + r1[j];
                q[j] = r0[j] * r0[j] + r1[j] * r1[j];
            }
            #pragma unroll
            for (int m = 16; m > 0; m >>= 1) {
                #pragma unroll
                for (int j = 0; j < 4; j++) {
                    s[j] += __shfl_xor_sync(0xffffffff, s[j], m);
                    q[j] += __shfl_xor_sync(0xffffffff, q[j], m);
                }
            }
            #pragma unroll
            for (int j = 0; j < 4; j++) {
                float mu  = s[j] * (1.f / 64.f);
                float var = q[j] * (1.f / 64.f) - mu * mu;
                float inv = rsqrtf(var + LN_EPS);
                r0[j] = fmaxf(fmaf((r0[j] - mu) * inv, q0w, q0b), 0.f);
                r1[j] = fmaxf(fmaf((r1[j] - mu) * inv, q1w, q1b), 0.f);
            }
        }

        // ---- store + GraphNorm partials ----
        #pragma unroll
        for (int j = 0; j < 4; j++) {
            int n = nbase + j;
            if (n < N) {
                long long b = (long long)n * C;
                h2[b + l]      = r0[j];
                h2[b + 32 + l] = r1[j];
                accS1_0 += r0[j];          accS1_1 += r1[j];
                accS2_0 += r0[j] * r0[j];  accS2_1 += r1[j] * r1[j];
            }
        }
        __syncwarp();
    }

    atomicAdd(&sS1[l],      accS1_0);
    atomicAdd(&sS1[l + 32], accS1_1);
    atomicAdd(&sS2[l],      accS2_0);
    atomicAdd(&sS2[l + 32], accS2_1);
    __syncthreads();
    if (tid < 64) {
        atomicAdd(&S1[tid], sS1[tid]);
        atomicAdd(&S2[tid], sS2[tid]);
    }
}

// ---------------------------------------------------------------------------
// K3: fused stats finalize + elementwise apply  out = A[c]*h + B[c]
// ---------------------------------------------------------------------------
__global__ void k_apply(const float4* __restrict__ h4,
                        const float* __restrict__ S1, const float* __restrict__ S2,
                        const float* __restrict__ gw, const float* __restrict__ gb,
                        const float* __restrict__ ga,
                        float4* __restrict__ out4, long long n4, float invN) {
    __shared__ float sA[64], sB[64];
    if (threadIdx.x < 64) {
        int c = threadIdx.x;
        float m  = S1[c] * invN;
        float e2 = S2[c] * invN;
        float a  = ga[c];
        float var = e2 - 2.f * a * m * m + a * a * m * m;
        float Ac  = gw[c] * rsqrtf(var + GN_EPS);
        sA[c] = Ac;
        sB[c] = gb[c] - Ac * a * m;
    }
    __syncthreads();
    long long i = (long long)blockIdx.x * blockDim.x + threadIdx.x;
    long long stride = (long long)gridDim.x * blockDim.x;
    for (long long j = i; j < n4; j += stride) {
        float4 v = h4[j];
        int c = (int)((j * 4) & 63);
        v.x = fmaf(sA[c + 0], v.x, sB[c + 0]);
        v.y = fmaf(sA[c + 1], v.y, sB[c + 1]);
        v.z = fmaf(sA[c + 2], v.z, sB[c + 2]);
        v.w = fmaf(sA[c + 3], v.w, sB[c + 3]);
        out4[j] = v;
    }
}

// ---------------------------------------------------------------------------
extern "C" void kernel_launch(void* const* d_in, const int* in_sizes, int n_in,
                              void* d_out, int out_size) {
    const float*     x    = (const float*)d_in[0];
    const long long* ei   = (const long long*)d_in[1];
    const float*     W0   = (const float*)d_in[2];
    const float*     ln0w = (const float*)d_in[3];
    const float*     ln0b = (const float*)d_in[4];
    const float*     W1   = (const float*)d_in[5];
    const float*     ln1w = (const float*)d_in[6];
    const float*     ln1b = (const float*)d_in[7];
    const float*     gnw  = (const float*)d_in[8];
    const float*     gnb  = (const float*)d_in[9];
    const float*     gna  = (const float*)d_in[10];
    float*           out  = (float*)d_out;

    int N = in_sizes[0] / C;
    int E = in_sizes[1] / 2;
    if (N > MAXN) N = MAXN;
    if (E > MAXE) E = MAXE;

    float *agg, *h2, *S1, *S2;
    cudaGetSymbolAddress((void**)&agg, g_agg);
    cudaGetSymbolAddress((void**)&h2,  g_h2);
    cudaGetSymbolAddress((void**)&S1,  g_S1);
    cudaGetSymbolAddress((void**)&S2,  g_S2);

    long long nelem = (long long)N * C;
    long long n4 = nelem / 4;

    // K0: agg = x, zero stats
    {
        int blocks = (int)((n4 + 255) / 256);
        if (blocks > 1184) blocks = 1184;
        k_init<<<blocks, 256>>>((const float4*)x, (float4*)agg, n4, S1, S2);
    }
    // K1: scatter-add (vector atomics)
    {
        long long threads = (long long)E * 16;
        int blocks = (int)((threads + 255) / 256);
        k_scatter<<<blocks, 256>>>(x, ei, agg, E, N);
    }
    // K2: MLP + partial GraphNorm stats (persistent, 4 nodes/warp)
    {
        int groups = (N + 31) / 32;
        int blocks = groups < 592 ? groups : 592;
        k_mlp<<<blocks, 256>>>(agg, W0, ln0w, ln0b, W1, ln1w, ln1b,
                               h2, S1, S2, N);
    }
    // K3: fused stats + apply
    {
        int blocks = (int)((n4 + 255) / 256);
        if (blocks > 1184) blocks = 1184;
        k_apply<<<blocks, 256>>>((const float4*)h2, S1, S2, gnw, gnb, gna,
                                 (float4*)out, n4, 1.0f / (float)N);
    }
}